// round 5
// baseline (speedup 1.0000x reference)
#include <cuda_runtime.h>
#include <cuda_fp16.h>
#include <cstdint>

// ---------------- scratch (__device__ globals; no allocs allowed) ----------------
__device__ float g_xt[32ll * 1024 * 256];      // x transposed: (bc, t, d)
__device__ float g_qk[32ll * 1024 * 512];      // Q,K: (bc, t, 512)
__device__ float g_vt[32ll * 256 * 1024];      // V^T: (bc, d, t)
__device__ float g_scores[32ll * 1024 * 1024]; // scores / probs
__device__ float g_attnO[32ll * 1024 * 256];   // attention out

__device__ __forceinline__ uint32_t smem_u32(const void* p) {
    uint32_t a;
    asm("{ .reg .u64 t; cvta.to.shared.u64 t, %1; cvt.u32.u64 %0, t; }" : "=r"(a) : "l"(p));
    return a;
}

#define LDSM4(r0, r1, r2, r3, addr)                                               \
    asm volatile("ldmatrix.sync.aligned.m8n8.x4.shared.b16 {%0,%1,%2,%3}, [%4];"  \
                 : "=r"(r0), "=r"(r1), "=r"(r2), "=r"(r3) : "r"(addr))

#define MMA16816(c, a, b0, b1)                                                    \
    asm volatile("mma.sync.aligned.m16n8k16.row.col.f32.f16.f16.f32 "             \
                 "{%0,%1,%2,%3},{%4,%5,%6,%7},{%8,%9},{%0,%1,%2,%3};"             \
                 : "+f"((c)[0]), "+f"((c)[1]), "+f"((c)[2]), "+f"((c)[3])         \
                 : "r"((a)[0]), "r"((a)[1]), "r"((a)[2]), "r"((a)[3]),            \
                   "r"(b0), "r"(b1))

// SMEM tile layout: 128 rows x 32 halves, padded to 40 halves (80 B) per row.
#define PITCHB   80
#define TILE_B   (128 * PITCHB)            // 10240 B
#define OFF_AH   0
#define OFF_AL   TILE_B
#define OFF_BH   (2 * TILE_B)
#define OFF_BL   (3 * TILE_B)
#define BUF_B    (4 * TILE_B)              // 40960 B per stage
#define SMEM_BYTES (2 * BUF_B)             // 81920 B

// float4 -> fp16 hi/lo pairs (each as 2x half2 packed in uint2)
__device__ __forceinline__ void cvt4(float4 v, uint2& h, uint2& l) {
    __half2 h01 = __floats2half2_rn(v.x, v.y);
    __half2 h23 = __floats2half2_rn(v.z, v.w);
    float2 f01 = __half22float2(h01);
    float2 f23 = __half22float2(h23);
    __half2 l01 = __floats2half2_rn(v.x - f01.x, v.y - f01.y);
    __half2 l23 = __floats2half2_rn(v.z - f23.x, v.w - f23.y);
    h.x = *reinterpret_cast<uint32_t*>(&h01);
    h.y = *reinterpret_cast<uint32_t*>(&h23);
    l.x = *reinterpret_cast<uint32_t*>(&l01);
    l.y = *reinterpret_cast<uint32_t*>(&l23);
}

// C[128 x 128 tile] = A(m,k) . B(n,k)^T with fp32-equivalent accuracy.
// A: lda k-contiguous rows. B: ldb k-contiguous rows. C row-major ldc.
// qkv_mode: output cols >= 512 go transposed into VT instead of C.
__global__ __launch_bounds__(256) void hgemm(
    const float* __restrict__ A, const float* __restrict__ B,
    float* __restrict__ C, float* __restrict__ VT,
    int K, int lda, int ldb, int ldc,
    long long sA, long long sB, long long sC,
    float alpha, const float* __restrict__ bias_n,
    const int* __restrict__ maskp, long long sMask, int qkv_mode)
{
    extern __shared__ char smem[];
    const uint32_t sbase = smem_u32(smem);
    const int tid = threadIdx.x;
    const int wid = tid >> 5, lane = tid & 31;
    const int bz = blockIdx.z;
    const int n0 = blockIdx.x * 128, m0 = blockIdx.y * 128;
    const int warp_m = wid & 1, warp_n = wid >> 1;   // 2 x 4 warp grid

    const float* Ab = A + bz * sA + (long long)m0 * lda;
    const float* Bb = B + bz * sB + (long long)n0 * ldb;

    float acc[4][4][4];
#pragma unroll
    for (int mt = 0; mt < 4; mt++)
#pragma unroll
        for (int nt = 0; nt < 4; nt++)
#pragma unroll
            for (int r = 0; r < 4; r++) acc[mt][nt][r] = 0.f;

    // global staging registers
    float4 ra[4], rb[4];
    const int ldr = tid >> 3;        // row handled by this thread (base)
    const int ldc4 = tid & 7;        // float4 column

    auto LOAD = [&](int k0) {
#pragma unroll
        for (int i = 0; i < 4; i++) {
            int r = ldr + i * 32;
            ra[i] = *reinterpret_cast<const float4*>(Ab + (long long)r * lda + k0 + ldc4 * 4);
            rb[i] = *reinterpret_cast<const float4*>(Bb + (long long)r * ldb + k0 + ldc4 * 4);
        }
    };
    auto STORE = [&](int buf) {
        char* base = smem + buf * BUF_B;
#pragma unroll
        for (int i = 0; i < 4; i++) {
            int r = ldr + i * 32;
            uint32_t off = (uint32_t)(r * PITCHB + ldc4 * 8);
            uint2 h, l;
            cvt4(ra[i], h, l);
            *reinterpret_cast<uint2*>(base + OFF_AH + off) = h;
            *reinterpret_cast<uint2*>(base + OFF_AL + off) = l;
            cvt4(rb[i], h, l);
            *reinterpret_cast<uint2*>(base + OFF_BH + off) = h;
            *reinterpret_cast<uint2*>(base + OFF_BL + off) = l;
        }
    };

    // lane-derived ldmatrix row/col offsets
    const int a_row = warp_m * 64 + (lane & 7) + ((lane >> 3) & 1) * 8;
    const int a_kq  = (lane >> 4) * 8;
    const int b_row = warp_n * 32 + (lane >> 4) * 8 + (lane & 7);
    const int b_kq  = ((lane >> 3) & 1) * 8;

    // Term-separated schedule: consecutive MMAs always target different
    // accumulators (reuse distance 4) to break HMMA RAW chains.
    auto COMPUTE = [&](int buf) {
        const uint32_t o = sbase + buf * BUF_B;
#pragma unroll
        for (int s = 0; s < 2; s++) {
            uint32_t bh[8], bl[8];
#pragma unroll
            for (int p = 0; p < 2; p++) {
                uint32_t boff = (uint32_t)((b_row + p * 16) * PITCHB + (s * 16 + b_kq) * 2);
                LDSM4(bh[p * 4 + 0], bh[p * 4 + 1], bh[p * 4 + 2], bh[p * 4 + 3], o + OFF_BH + boff);
                LDSM4(bl[p * 4 + 0], bl[p * 4 + 1], bl[p * 4 + 2], bl[p * 4 + 3], o + OFF_BL + boff);
            }
#pragma unroll
            for (int mt = 0; mt < 4; mt++) {
                uint32_t ah[4], al[4];
                uint32_t aoff = (uint32_t)((a_row + mt * 16) * PITCHB + (s * 16 + a_kq) * 2);
                LDSM4(ah[0], ah[1], ah[2], ah[3], o + OFF_AH + aoff);
                LDSM4(al[0], al[1], al[2], al[3], o + OFF_AL + aoff);
#pragma unroll
                for (int nt = 0; nt < 4; nt++) {
                    const int i0 = (nt >> 1) * 4 + (nt & 1) * 2;
                    MMA16816(acc[mt][nt], ah, bh[i0], bh[i0 + 1]);
                }
#pragma unroll
                for (int nt = 0; nt < 4; nt++) {
                    const int i0 = (nt >> 1) * 4 + (nt & 1) * 2;
                    MMA16816(acc[mt][nt], ah, bl[i0], bl[i0 + 1]);
                }
#pragma unroll
                for (int nt = 0; nt < 4; nt++) {
                    const int i0 = (nt >> 1) * 4 + (nt & 1) * 2;
                    MMA16816(acc[mt][nt], al, bh[i0], bh[i0 + 1]);
                }
            }
        }
    };

    const int nch = K >> 5;
    LOAD(0);
    for (int ch = 0; ch < nch; ch++) {
        STORE(ch & 1);
        __syncthreads();
        if (ch + 1 < nch) LOAD((ch + 1) << 5);
        COMPUTE(ch & 1);
    }

    // ---------------- epilogue ----------------
    const float NEG_INF = __int_as_float(0xff800000);
    float* C_bz = C + bz * sC;
    float* VT_bz = VT ? (VT + bz * (256ll * 1024)) : nullptr;
    const int* mk = maskp ? (maskp + bz * sMask) : nullptr;
    const int gid = lane >> 2, q4 = lane & 3;

#pragma unroll
    for (int mt = 0; mt < 4; mt++) {
#pragma unroll
        for (int nt = 0; nt < 4; nt++) {
            const int col = n0 + warp_n * 32 + nt * 8 + q4 * 2;
            const int vmode = qkv_mode && (col >= 512);
            float b0 = 0.f, b1 = 0.f;
            if (bias_n) { b0 = bias_n[col]; b1 = bias_n[col + 1]; }
#pragma unroll
            for (int h = 0; h < 2; h++) {
                const int row = m0 + warp_m * 64 + mt * 16 + gid + h * 8;
                float v0 = acc[mt][nt][h * 2 + 0] * alpha + b0;
                float v1 = acc[mt][nt][h * 2 + 1] * alpha + b1;
                if (mk) {
                    int2 mv = *reinterpret_cast<const int2*>(mk + (long long)row * 1024 + col);
                    if (mv.x != 0) v0 = NEG_INF;
                    if (mv.y != 0) v1 = NEG_INF;
                }
                if (!vmode) {
                    *reinterpret_cast<float2*>(C_bz + (long long)row * ldc + col) =
                        make_float2(v0, v1);
                } else {
                    VT_bz[(long long)(col - 512) * 1024 + row] = v0;
                    VT_bz[(long long)(col - 511) * 1024 + row] = v1;
                }
            }
        }
    }
}

// ---------------- transpose x: (bc, 256, 1024) -> (bc, 1024, 256) ----------------
__global__ __launch_bounds__(256) void transpose_kernel(
    const float* __restrict__ x, float* __restrict__ xt)
{
    __shared__ float tile[32][33];
    const int bz = blockIdx.z;
    const float* xs = x + (long long)bz * 256 * 1024;
    float* xd = xt + (long long)bz * 1024 * 256;
    const int t0 = blockIdx.x * 32, d0 = blockIdx.y * 32;
    const int tx = threadIdx.x, ty = threadIdx.y;
#pragma unroll
    for (int k = 0; k < 4; k++)
        tile[ty + k * 8][tx] = xs[(long long)(d0 + ty + k * 8) * 1024 + t0 + tx];
    __syncthreads();
#pragma unroll
    for (int k = 0; k < 4; k++)
        xd[(long long)(t0 + ty + k * 8) * 256 + d0 + tx] = tile[tx][ty + k * 8];
}

// ---------------- row softmax over length-1024 rows ----------------
__global__ __launch_bounds__(256) void softmax_kernel(float* __restrict__ S)
{
    const long long row = blockIdx.x;
    float* p = S + row * 1024;
    const int tid = threadIdx.x;

    float4 v = reinterpret_cast<float4*>(p)[tid];
    float m = fmaxf(fmaxf(v.x, v.y), fmaxf(v.z, v.w));
#pragma unroll
    for (int o = 16; o; o >>= 1) m = fmaxf(m, __shfl_xor_sync(0xffffffffu, m, o));

    __shared__ float red[8];
    if ((tid & 31) == 0) red[tid >> 5] = m;
    __syncthreads();
    float mm = red[0];
#pragma unroll
    for (int w = 1; w < 8; w++) mm = fmaxf(mm, red[w]);
    __syncthreads();

    float e0 = (v.x <= -1e30f) ? 0.f : __expf(v.x - mm);
    float e1 = (v.y <= -1e30f) ? 0.f : __expf(v.y - mm);
    float e2 = (v.z <= -1e30f) ? 0.f : __expf(v.z - mm);
    float e3 = (v.w <= -1e30f) ? 0.f : __expf(v.w - mm);

    float s = e0 + e1 + e2 + e3;
#pragma unroll
    for (int o = 16; o; o >>= 1) s += __shfl_xor_sync(0xffffffffu, s, o);
    if ((tid & 31) == 0) red[tid >> 5] = s;
    __syncthreads();
    float tot = red[0];
#pragma unroll
    for (int w = 1; w < 8; w++) tot += red[w];

    float inv = 1.0f / tot;
    reinterpret_cast<float4*>(p)[tid] = make_float4(e0 * inv, e1 * inv, e2 * inv, e3 * inv);
}

extern "C" void kernel_launch(void* const* d_in, const int* in_sizes, int n_in,
                              void* d_out, int out_size)
{
    const float* x     = (const float*)d_in[0];   // (8,4,256,1024)
    const int*   mask  = (const int*)d_in[1];     // (8,4,1024,1024) bool -> int32
    const float* w_qkv = (const float*)d_in[2];   // (768,256)
    const float* b_qkv = (const float*)d_in[3];   // (768,)
    const float* w_out = (const float*)d_in[4];   // (256,256)
    const float* b_out = (const float*)d_in[5];   // (256,)
    float*       out   = (float*)d_out;           // (8,4,1024,256)

    float *xt, *qk, *vt, *scores, *attnO;
    cudaGetSymbolAddress((void**)&xt,     g_xt);
    cudaGetSymbolAddress((void**)&qk,     g_qk);
    cudaGetSymbolAddress((void**)&vt,     g_vt);
    cudaGetSymbolAddress((void**)&scores, g_scores);
    cudaGetSymbolAddress((void**)&attnO,  g_attnO);

    cudaFuncSetAttribute(hgemm, cudaFuncAttributeMaxDynamicSharedMemorySize, SMEM_BYTES);

    // 0) transpose x -> xt (bc, t, d)
    transpose_kernel<<<dim3(32, 8, 32), dim3(32, 8)>>>(x, xt);

    // 1) QKV: (1024 x 768) = xt (1024,256) @ w_qkv^T + b; Q,K -> qk, V -> vt (transposed)
    hgemm<<<dim3(6, 8, 32), 256, SMEM_BYTES>>>(
        xt, w_qkv, qk, vt,
        256, 256, 256, 512,
        1024ll * 256, 0, 1024ll * 512,
        1.0f, b_qkv, nullptr, 0, 1);

    // 2) scores = scale * Q @ K^T, mask -> -inf
    hgemm<<<dim3(8, 8, 32), 256, SMEM_BYTES>>>(
        qk, qk + 256, scores, nullptr,
        256, 512, 512, 1024,
        1024ll * 512, 1024ll * 512, 1024ll * 1024,
        0.0625f, nullptr, mask, 1024ll * 1024, 0);

    // 3) softmax
    softmax_kernel<<<32 * 1024, 256>>>(scores);

    // 4) attnO = P @ V   (V^T is (d, t), k-contiguous rows for B)
    hgemm<<<dim3(2, 8, 32), 256, SMEM_BYTES>>>(
        scores, vt, attnO, nullptr,
        1024, 1024, 1024, 256,
        1024ll * 1024, 256ll * 1024, 1024ll * 256,
        1.0f, nullptr, nullptr, 0, 0);

    // 5) out = attnO @ w_out^T + b_out
    hgemm<<<dim3(2, 8, 32), 256, SMEM_BYTES>>>(
        attnO, w_out, out, nullptr,
        256, 256, 256, 256,
        1024ll * 256, 0, 1024ll * 256,
        1.0f, b_out, nullptr, 0, 0);
}

// round 6
// speedup vs baseline: 1.0536x; 1.0536x over previous
#include <cuda_runtime.h>
#include <cuda_fp16.h>
#include <cstdint>

// ---------------- scratch (__device__ globals; no allocs allowed) ----------------
__device__ __half g_xt_h[32ll * 1024 * 256], g_xt_l[32ll * 1024 * 256];   // x^T hi/lo
__device__ __half g_qk_h[32ll * 1024 * 512], g_qk_l[32ll * 1024 * 512];   // Q,K hi/lo
__device__ __half g_vt_h[32ll * 256 * 1024], g_vt_l[32ll * 256 * 1024];   // V^T hi/lo
__device__ float  g_scores[32ll * 1024 * 1024];                           // fp32 scores
__device__ __half g_p_h[32ll * 1024 * 1024], g_p_l[32ll * 1024 * 1024];   // probs hi/lo
__device__ __half g_ao_h[32ll * 1024 * 256], g_ao_l[32ll * 1024 * 256];   // attn out hi/lo
__device__ __half g_wq_h[768 * 256], g_wq_l[768 * 256];
__device__ __half g_wo_h[256 * 256], g_wo_l[256 * 256];

__device__ __forceinline__ uint32_t smem_u32(const void* p) {
    uint32_t a;
    asm("{ .reg .u64 t; cvta.to.shared.u64 t, %1; cvt.u32.u64 %0, t; }" : "=r"(a) : "l"(p));
    return a;
}

#define CP_ASYNC16(dst, src) \
    asm volatile("cp.async.cg.shared.global [%0], [%1], 16;" :: "r"(dst), "l"(src))
#define CP_COMMIT() asm volatile("cp.async.commit_group;")
#define CP_WAIT(n)  asm volatile("cp.async.wait_group %0;" :: "n"(n))

#define LDSM4(r0, r1, r2, r3, addr)                                               \
    asm volatile("ldmatrix.sync.aligned.m8n8.x4.shared.b16 {%0,%1,%2,%3}, [%4];"  \
                 : "=r"(r0), "=r"(r1), "=r"(r2), "=r"(r3) : "r"(addr))

#define MMA16816(c, a, b0, b1)                                                    \
    asm volatile("mma.sync.aligned.m16n8k16.row.col.f32.f16.f16.f32 "             \
                 "{%0,%1,%2,%3},{%4,%5,%6,%7},{%8,%9},{%0,%1,%2,%3};"             \
                 : "+f"((c)[0]), "+f"((c)[1]), "+f"((c)[2]), "+f"((c)[3])         \
                 : "r"((a)[0]), "r"((a)[1]), "r"((a)[2]), "r"((a)[3]),            \
                   "r"(b0), "r"(b1))

// SMEM tile: 128 rows x 32 halves, padded to 80 B / row (16B-aligned, conflict-free).
#define PITCHB   80
#define TILE_B   (128 * PITCHB)            // 10240 B
#define OFF_AH   0
#define OFF_AL   TILE_B
#define OFF_BH   (2 * TILE_B)
#define OFF_BL   (3 * TILE_B)
#define BUF_B    (4 * TILE_B)              // 40960 B / stage
#define SMEM_BYTES (2 * BUF_B)             // 81920 B

__device__ __forceinline__ void split2(float v0, float v1, __half2& h, __half2& l) {
    __half h0 = __float2half_rn(v0), h1 = __float2half_rn(v1);
    h = __halves2half2(h0, h1);
    l = __halves2half2(__float2half_rn(v0 - __half2float(h0)),
                       __float2half_rn(v1 - __half2float(h1)));
}

// C[128 x 128 tile] = A(m,k) . B(n,k)^T, fp32-equivalent via fp16 hi/lo 3-pass.
// Inputs are pre-split hi/lo half arrays (k-contiguous rows, ld in halves).
// Outputs: C32 (fp32, +alpha/bias/mask) and/or Ch/Cl (half pairs); qkv_mode routes
// cols >= 512 transposed into VTh/VTl.
__global__ __launch_bounds__(256, 2) void hgemm(
    const __half* __restrict__ Ah, const __half* __restrict__ Al,
    const __half* __restrict__ Bh, const __half* __restrict__ Bl,
    float* __restrict__ C32, __half* __restrict__ Ch, __half* __restrict__ Cl,
    __half* __restrict__ VTh, __half* __restrict__ VTl,
    int K, int lda, int ldb, int ldc,
    long long sA, long long sB, long long sC,
    float alpha, const float* __restrict__ bias_n,
    const int* __restrict__ maskp, long long sMask, int qkv_mode)
{
    extern __shared__ char smem[];
    const uint32_t sbase = smem_u32(smem);
    const int tid = threadIdx.x;
    const int wid = tid >> 5, lane = tid & 31;
    const int bz = blockIdx.z;
    const int n0 = blockIdx.x * 128, m0 = blockIdx.y * 128;
    const int warp_m = wid & 1, warp_n = wid >> 1;   // 2 x 4 warp grid

    const __half* Ahb = Ah + bz * sA + (long long)m0 * lda;
    const __half* Alb = Al + bz * sA + (long long)m0 * lda;
    const __half* Bhb = Bh + bz * sB + (long long)n0 * ldb;
    const __half* Blb = Bl + bz * sB + (long long)n0 * ldb;

    float acc[4][4][4];
#pragma unroll
    for (int mt = 0; mt < 4; mt++)
#pragma unroll
        for (int nt = 0; nt < 4; nt++)
#pragma unroll
            for (int r = 0; r < 4; r++) acc[mt][nt][r] = 0.f;

    // cp.async tile fill: 4 tiles x 512 16B-chunks / 256 threads = 8 per thread
    auto CP_TILES = [&](int ch, int buf) {
        const int k0 = ch << 5;
        const uint32_t sb = sbase + buf * BUF_B;
#pragma unroll
        for (int i = 0; i < 2; i++) {
            const int c = tid + i * 256;            // 0..511
            const int row = c >> 2, part = c & 3;
            const uint32_t doff = (uint32_t)(row * PITCHB + part * 16);
            const long long goff = (long long)row * lda + k0 + part * 8;
            const long long gofb = (long long)row * ldb + k0 + part * 8;
            CP_ASYNC16(sb + OFF_AH + doff, Ahb + goff);
            CP_ASYNC16(sb + OFF_AL + doff, Alb + goff);
            CP_ASYNC16(sb + OFF_BH + doff, Bhb + gofb);
            CP_ASYNC16(sb + OFF_BL + doff, Blb + gofb);
        }
    };

    // lane-derived ldmatrix row/col offsets
    const int a_row = warp_m * 64 + (lane & 7) + ((lane >> 3) & 1) * 8;
    const int a_kq  = (lane >> 4) * 8;
    const int b_row = warp_n * 32 + (lane >> 4) * 8 + (lane & 7);
    const int b_kq  = ((lane >> 3) & 1) * 8;

    auto COMPUTE = [&](int buf) {
        const uint32_t o = sbase + buf * BUF_B;
#pragma unroll
        for (int s = 0; s < 2; s++) {
            uint32_t bh[8], bl[8];
#pragma unroll
            for (int p = 0; p < 2; p++) {
                uint32_t boff = (uint32_t)((b_row + p * 16) * PITCHB + (s * 16 + b_kq) * 2);
                LDSM4(bh[p * 4 + 0], bh[p * 4 + 1], bh[p * 4 + 2], bh[p * 4 + 3], o + OFF_BH + boff);
                LDSM4(bl[p * 4 + 0], bl[p * 4 + 1], bl[p * 4 + 2], bl[p * 4 + 3], o + OFF_BL + boff);
            }
#pragma unroll
            for (int mt = 0; mt < 4; mt++) {
                uint32_t ah[4], al[4];
                uint32_t aoff = (uint32_t)((a_row + mt * 16) * PITCHB + (s * 16 + a_kq) * 2);
                LDSM4(ah[0], ah[1], ah[2], ah[3], o + OFF_AH + aoff);
                LDSM4(al[0], al[1], al[2], al[3], o + OFF_AL + aoff);
#pragma unroll
                for (int nt = 0; nt < 4; nt++) {
                    const int i0 = (nt >> 1) * 4 + (nt & 1) * 2;
                    MMA16816(acc[mt][nt], ah, bh[i0], bh[i0 + 1]);
                    MMA16816(acc[mt][nt], ah, bl[i0], bl[i0 + 1]);
                    MMA16816(acc[mt][nt], al, bh[i0], bh[i0 + 1]);
                }
            }
        }
    };

    const int nch = K >> 5;
    CP_TILES(0, 0);
    CP_COMMIT();
    for (int ch = 0; ch < nch; ch++) {
        if (ch + 1 < nch) {
            CP_TILES(ch + 1, (ch + 1) & 1);
            CP_COMMIT();
            CP_WAIT(1);
        } else {
            CP_WAIT(0);
        }
        __syncthreads();
        COMPUTE(ch & 1);
        __syncthreads();   // guard buffer reuse by next iteration's cp.async
    }

    // ---------------- epilogue ----------------
    const float NEG_INF = __int_as_float(0xff800000);
    float* C32b = C32 ? (C32 + bz * sC) : nullptr;
    __half* Chb = Ch ? (Ch + bz * sC) : nullptr;
    __half* Clb = Cl ? (Cl + bz * sC) : nullptr;
    __half* VThb = VTh ? (VTh + bz * (256ll * 1024)) : nullptr;
    __half* VTlb = VTl ? (VTl + bz * (256ll * 1024)) : nullptr;
    const int* mk = maskp ? (maskp + bz * sMask) : nullptr;
    const int gid = lane >> 2, q4 = lane & 3;

#pragma unroll
    for (int mt = 0; mt < 4; mt++) {
#pragma unroll
        for (int nt = 0; nt < 4; nt++) {
            const int col = n0 + warp_n * 32 + nt * 8 + q4 * 2;
            const int vmode = qkv_mode && (col >= 512);
            float b0 = 0.f, b1 = 0.f;
            if (bias_n) { b0 = bias_n[col]; b1 = bias_n[col + 1]; }
#pragma unroll
            for (int h = 0; h < 2; h++) {
                const int row = m0 + warp_m * 64 + mt * 16 + gid + h * 8;
                float v0 = acc[mt][nt][h * 2 + 0] * alpha + b0;
                float v1 = acc[mt][nt][h * 2 + 1] * alpha + b1;
                if (mk) {
                    int2 mv = *reinterpret_cast<const int2*>(mk + (long long)row * 1024 + col);
                    if (mv.x != 0) v0 = NEG_INF;
                    if (mv.y != 0) v1 = NEG_INF;
                }
                if (C32b)
                    *reinterpret_cast<float2*>(C32b + (long long)row * ldc + col) =
                        make_float2(v0, v1);
                if (!vmode) {
                    if (Chb) {
                        __half2 hh, ll;
                        split2(v0, v1, hh, ll);
                        *reinterpret_cast<__half2*>(Chb + (long long)row * ldc + col) = hh;
                        *reinterpret_cast<__half2*>(Clb + (long long)row * ldc + col) = ll;
                    }
                } else {
                    __half h0 = __float2half_rn(v0);
                    __half h1 = __float2half_rn(v1);
                    VThb[(long long)(col - 512) * 1024 + row] = h0;
                    VThb[(long long)(col - 511) * 1024 + row] = h1;
                    VTlb[(long long)(col - 512) * 1024 + row] = __float2half_rn(v0 - __half2float(h0));
                    VTlb[(long long)(col - 511) * 1024 + row] = __float2half_rn(v1 - __half2float(h1));
                }
            }
        }
    }
}

// ---------------- transpose x: (bc, 256, 1024) -> (bc, 1024, 256) hi/lo halves ----
__global__ __launch_bounds__(256) void transpose_kernel(
    const float* __restrict__ x, __half* __restrict__ xh, __half* __restrict__ xl)
{
    __shared__ float tile[32][33];
    const int bz = blockIdx.z;
    const float* xs = x + (long long)bz * 256 * 1024;
    __half* xhd = xh + (long long)bz * 1024 * 256;
    __half* xld = xl + (long long)bz * 1024 * 256;
    const int t0 = blockIdx.x * 32, d0 = blockIdx.y * 32;
    const int tx = threadIdx.x, ty = threadIdx.y;
#pragma unroll
    for (int k = 0; k < 4; k++)
        tile[ty + k * 8][tx] = xs[(long long)(d0 + ty + k * 8) * 1024 + t0 + tx];
    __syncthreads();
#pragma unroll
    for (int k = 0; k < 4; k++) {
        float v = tile[tx][ty + k * 8];
        __half h = __float2half_rn(v);
        long long o = (long long)(t0 + ty + k * 8) * 256 + d0 + tx;
        xhd[o] = h;
        xld[o] = __float2half_rn(v - __half2float(h));
    }
}

// ---------------- weight fp32 -> hi/lo halves ----------------
__global__ void cvt_kernel(const float* __restrict__ w,
                           __half* __restrict__ h, __half* __restrict__ l, int n)
{
    int i = blockIdx.x * 256 + threadIdx.x;
    if (i < n) {
        float v = w[i];
        __half hh = __float2half_rn(v);
        h[i] = hh;
        l[i] = __float2half_rn(v - __half2float(hh));
    }
}

// ---------------- row softmax (fp32 in) -> P hi/lo halves ----------------
__global__ __launch_bounds__(256) void softmax_kernel(
    const float* __restrict__ S, __half* __restrict__ Ph, __half* __restrict__ Pl)
{
    const long long row = blockIdx.x;
    const float* p = S + row * 1024;
    const int tid = threadIdx.x;

    float4 v = reinterpret_cast<const float4*>(p)[tid];
    float m = fmaxf(fmaxf(v.x, v.y), fmaxf(v.z, v.w));
#pragma unroll
    for (int o = 16; o; o >>= 1) m = fmaxf(m, __shfl_xor_sync(0xffffffffu, m, o));

    __shared__ float red[8];
    if ((tid & 31) == 0) red[tid >> 5] = m;
    __syncthreads();
    float mm = red[0];
#pragma unroll
    for (int w = 1; w < 8; w++) mm = fmaxf(mm, red[w]);
    __syncthreads();

    float e0 = (v.x <= -1e30f) ? 0.f : __expf(v.x - mm);
    float e1 = (v.y <= -1e30f) ? 0.f : __expf(v.y - mm);
    float e2 = (v.z <= -1e30f) ? 0.f : __expf(v.z - mm);
    float e3 = (v.w <= -1e30f) ? 0.f : __expf(v.w - mm);

    float s = e0 + e1 + e2 + e3;
#pragma unroll
    for (int o = 16; o; o >>= 1) s += __shfl_xor_sync(0xffffffffu, s, o);
    if ((tid & 31) == 0) red[tid >> 5] = s;
    __syncthreads();
    float tot = red[0];
#pragma unroll
    for (int w = 1; w < 8; w++) tot += red[w];

    float inv = 1.0f / tot;
    float o0 = e0 * inv, o1 = e1 * inv, o2 = e2 * inv, o3 = e3 * inv;
    __half2 h01, l01, h23, l23;
    split2(o0, o1, h01, l01);
    split2(o2, o3, h23, l23);
    *reinterpret_cast<uint2*>(Ph + row * 1024 + tid * 4) =
        make_uint2(*reinterpret_cast<uint32_t*>(&h01), *reinterpret_cast<uint32_t*>(&h23));
    *reinterpret_cast<uint2*>(Pl + row * 1024 + tid * 4) =
        make_uint2(*reinterpret_cast<uint32_t*>(&l01), *reinterpret_cast<uint32_t*>(&l23));
}

extern "C" void kernel_launch(void* const* d_in, const int* in_sizes, int n_in,
                              void* d_out, int out_size)
{
    const float* x     = (const float*)d_in[0];   // (8,4,256,1024)
    const int*   mask  = (const int*)d_in[1];     // (8,4,1024,1024) bool -> int32
    const float* w_qkv = (const float*)d_in[2];   // (768,256)
    const float* b_qkv = (const float*)d_in[3];   // (768,)
    const float* w_out = (const float*)d_in[4];   // (256,256)
    const float* b_out = (const float*)d_in[5];   // (256,)
    float*       out   = (float*)d_out;           // (8,4,1024,256)

    __half *xth, *xtl, *qkh, *qkl, *vth, *vtl, *ph, *pl, *aoh, *aol, *wqh, *wql, *woh, *wol;
    float* scores;
    cudaGetSymbolAddress((void**)&xth, g_xt_h); cudaGetSymbolAddress((void**)&xtl, g_xt_l);
    cudaGetSymbolAddress((void**)&qkh, g_qk_h); cudaGetSymbolAddress((void**)&qkl, g_qk_l);
    cudaGetSymbolAddress((void**)&vth, g_vt_h); cudaGetSymbolAddress((void**)&vtl, g_vt_l);
    cudaGetSymbolAddress((void**)&ph,  g_p_h);  cudaGetSymbolAddress((void**)&pl,  g_p_l);
    cudaGetSymbolAddress((void**)&aoh, g_ao_h); cudaGetSymbolAddress((void**)&aol, g_ao_l);
    cudaGetSymbolAddress((void**)&wqh, g_wq_h); cudaGetSymbolAddress((void**)&wql, g_wq_l);
    cudaGetSymbolAddress((void**)&woh, g_wo_h); cudaGetSymbolAddress((void**)&wol, g_wo_l);
    cudaGetSymbolAddress((void**)&scores, g_scores);

    cudaFuncSetAttribute(hgemm, cudaFuncAttributeMaxDynamicSharedMemorySize, SMEM_BYTES);

    // 0) converters
    transpose_kernel<<<dim3(32, 8, 32), dim3(32, 8)>>>(x, xth, xtl);
    cvt_kernel<<<768, 256>>>(w_qkv, wqh, wql, 768 * 256);
    cvt_kernel<<<256, 256>>>(w_out, woh, wol, 256 * 256);

    // 1) QKV: Q,K -> qk halves; V -> vt halves (transposed)
    hgemm<<<dim3(6, 8, 32), 256, SMEM_BYTES>>>(
        xth, xtl, wqh, wql,
        nullptr, qkh, qkl, vth, vtl,
        256, 256, 256, 512,
        1024ll * 256, 0, 1024ll * 512,
        1.0f, b_qkv, nullptr, 0, 1);

    // 2) scores (fp32) = scale * Q @ K^T, mask -> -inf
    hgemm<<<dim3(8, 8, 32), 256, SMEM_BYTES>>>(
        qkh, qkl, qkh + 256, qkl + 256,
        scores, nullptr, nullptr, nullptr, nullptr,
        256, 512, 512, 1024,
        1024ll * 512, 1024ll * 512, 1024ll * 1024,
        0.0625f, nullptr, mask, 1024ll * 1024, 0);

    // 3) softmax -> P halves
    softmax_kernel<<<32 * 1024, 256>>>(scores, ph, pl);

    // 4) attnO halves = P @ V
    hgemm<<<dim3(2, 8, 32), 256, SMEM_BYTES>>>(
        ph, pl, vth, vtl,
        nullptr, aoh, aol, nullptr, nullptr,
        1024, 1024, 1024, 256,
        1024ll * 1024, 256ll * 1024, 1024ll * 256,
        1.0f, nullptr, nullptr, 0, 0);

    // 5) out (fp32) = attnO @ w_out^T + b_out
    hgemm<<<dim3(2, 8, 32), 256, SMEM_BYTES>>>(
        aoh, aol, woh, wol,
        out, nullptr, nullptr, nullptr, nullptr,
        256, 256, 256, 256,
        1024ll * 256, 0, 1024ll * 256,
        1.0f, b_out, nullptr, 0, 0);
}

// round 7
// speedup vs baseline: 1.2073x; 1.1458x over previous
#include <cuda_runtime.h>
#include <cuda_fp16.h>
#include <cstdint>

// ---------------- scratch (__device__ globals; no allocs allowed) ----------------
__device__ __half g_xt_h[32ll * 1024 * 256], g_xt_l[32ll * 1024 * 256];   // x^T hi/lo
__device__ __half g_qk_h[32ll * 1024 * 512], g_qk_l[32ll * 1024 * 512];   // Q,K hi/lo
__device__ __half g_vt_h[32ll * 256 * 1024], g_vt_l[32ll * 256 * 1024];   // V^T hi/lo
__device__ float  g_scores[32ll * 1024 * 1024];                           // fp32 scores
__device__ __half g_p_h[32ll * 1024 * 1024], g_p_l[32ll * 1024 * 1024];   // probs hi/lo
__device__ __half g_ao_h[32ll * 1024 * 256], g_ao_l[32ll * 1024 * 256];   // attn out hi/lo
__device__ __half g_wq_h[768 * 256], g_wq_l[768 * 256];
__device__ __half g_wo_h[256 * 256], g_wo_l[256 * 256];

__device__ __forceinline__ uint32_t smem_u32(const void* p) {
    uint32_t a;
    asm("{ .reg .u64 t; cvta.to.shared.u64 t, %1; cvt.u32.u64 %0, t; }" : "=r"(a) : "l"(p));
    return a;
}

#define CP_ASYNC16(dst, src) \
    asm volatile("cp.async.cg.shared.global [%0], [%1], 16;" :: "r"(dst), "l"(src))
#define CP_COMMIT() asm volatile("cp.async.commit_group;")
#define CP_WAIT(n)  asm volatile("cp.async.wait_group %0;" :: "n"(n))

#define LDSM4(r0, r1, r2, r3, addr)                                               \
    asm volatile("ldmatrix.sync.aligned.m8n8.x4.shared.b16 {%0,%1,%2,%3}, [%4];"  \
                 : "=r"(r0), "=r"(r1), "=r"(r2), "=r"(r3) : "r"(addr))

#define MMA16816(c, a, b0, b1)                                                    \
    asm volatile("mma.sync.aligned.m16n8k16.row.col.f32.f16.f16.f32 "             \
                 "{%0,%1,%2,%3},{%4,%5,%6,%7},{%8,%9},{%0,%1,%2,%3};"             \
                 : "+f"((c)[0]), "+f"((c)[1]), "+f"((c)[2]), "+f"((c)[3])         \
                 : "r"((a)[0]), "r"((a)[1]), "r"((a)[2]), "r"((a)[3]),            \
                   "r"(b0), "r"(b1))

// Compact tile: 128 rows x 32 halves = 64 B/row, XOR-swizzled 16B chunks.
// Conflict-free for both cp.async fills and ldmatrix reads.
#define TILE_B   8192
#define OFF_AH   0
#define OFF_AL   8192
#define OFF_BH   16384
#define OFF_BL   24576
#define BUF_B    32768
#define NSTAGE   3
#define SMEM_BYTES (NSTAGE * BUF_B)        // 98304 B

// byte offset of (row, khalf) inside one tile
__device__ __forceinline__ uint32_t sws(int row, int khalf) {
    return (uint32_t)(row * 64 + ((((khalf >> 3) ^ (row >> 1)) & 3) << 4));
}

__device__ __forceinline__ void split2(float v0, float v1, __half2& h, __half2& l) {
    __half h0 = __float2half_rn(v0), h1 = __float2half_rn(v1);
    h = __halves2half2(h0, h1);
    l = __halves2half2(__float2half_rn(v0 - __half2float(h0)),
                       __float2half_rn(v1 - __half2float(h1)));
}

// C[128 x 128 tile] = A(m,k) . B(n,k)^T, fp32-equivalent via fp16 hi/lo 3-pass.
__global__ __launch_bounds__(256, 2) void hgemm(
    const __half* __restrict__ Ah, const __half* __restrict__ Al,
    const __half* __restrict__ Bh, const __half* __restrict__ Bl,
    float* __restrict__ C32, __half* __restrict__ Ch, __half* __restrict__ Cl,
    __half* __restrict__ VTh, __half* __restrict__ VTl,
    int K, int lda, int ldb, int ldc,
    long long sA, long long sB, long long sC,
    float alpha, const float* __restrict__ bias_n,
    const int* __restrict__ maskp, long long sMask, int qkv_mode)
{
    extern __shared__ char smem[];
    const uint32_t sbase = smem_u32(smem);
    const int tid = threadIdx.x;
    const int wid = tid >> 5, lane = tid & 31;
    const int bz = blockIdx.z;
    const int n0 = blockIdx.x * 128, m0 = blockIdx.y * 128;
    const int warp_m = wid & 1, warp_n = wid >> 1;   // 2 x 4 warp grid

    const __half* Ahb = Ah + bz * sA + (long long)m0 * lda;
    const __half* Alb = Al + bz * sA + (long long)m0 * lda;
    const __half* Bhb = Bh + bz * sB + (long long)n0 * ldb;
    const __half* Blb = Bl + bz * sB + (long long)n0 * ldb;

    float acc[4][4][4];
#pragma unroll
    for (int mt = 0; mt < 4; mt++)
#pragma unroll
        for (int nt = 0; nt < 4; nt++)
#pragma unroll
            for (int r = 0; r < 4; r++) acc[mt][nt][r] = 0.f;

    auto CP_TILES = [&](int ch, int buf) {
        const int k0 = ch << 5;
        const uint32_t sb = sbase + buf * BUF_B;
#pragma unroll
        for (int i = 0; i < 2; i++) {
            const int c = tid + i * 256;            // 0..511
            const int row = c >> 2, part = c & 3;
            const uint32_t doff = sws(row, part << 3);
            const long long goff = (long long)row * lda + k0 + part * 8;
            const long long gofb = (long long)row * ldb + k0 + part * 8;
            CP_ASYNC16(sb + OFF_AH + doff, Ahb + goff);
            CP_ASYNC16(sb + OFF_AL + doff, Alb + goff);
            CP_ASYNC16(sb + OFF_BH + doff, Bhb + gofb);
            CP_ASYNC16(sb + OFF_BL + doff, Blb + gofb);
        }
    };

    // lane-derived ldmatrix row/col bases
    const int a_row = warp_m * 64 + (lane & 7) + ((lane >> 3) & 1) * 8;
    const int a_kq  = (lane >> 4) * 8;
    const int b_row = warp_n * 32 + (lane >> 4) * 8 + (lane & 7);
    const int b_kq  = ((lane >> 3) & 1) * 8;

    auto COMPUTE = [&](int buf) {
        const uint32_t o = sbase + buf * BUF_B;
#pragma unroll
        for (int s = 0; s < 2; s++) {
            uint32_t bh[8], bl[8];
#pragma unroll
            for (int p = 0; p < 2; p++) {
                const int row = b_row + p * 16;
                const uint32_t boff = sws(row, s * 16 + b_kq);
                LDSM4(bh[p * 4 + 0], bh[p * 4 + 1], bh[p * 4 + 2], bh[p * 4 + 3], o + OFF_BH + boff);
                LDSM4(bl[p * 4 + 0], bl[p * 4 + 1], bl[p * 4 + 2], bl[p * 4 + 3], o + OFF_BL + boff);
            }
#pragma unroll
            for (int mt = 0; mt < 4; mt++) {
                uint32_t ah[4], al[4];
                const int row = a_row + mt * 16;
                const uint32_t aoff = sws(row, s * 16 + a_kq);
                LDSM4(ah[0], ah[1], ah[2], ah[3], o + OFF_AH + aoff);
                LDSM4(al[0], al[1], al[2], al[3], o + OFF_AL + aoff);
#pragma unroll
                for (int nt = 0; nt < 4; nt++) {
                    const int i0 = (nt >> 1) * 4 + (nt & 1) * 2;
                    MMA16816(acc[mt][nt], ah, bh[i0], bh[i0 + 1]);
                    MMA16816(acc[mt][nt], ah, bl[i0], bl[i0 + 1]);
                    MMA16816(acc[mt][nt], al, bh[i0], bh[i0 + 1]);
                }
            }
        }
    };

    // 3-stage pipeline, one barrier per chunk
    const int nch = K >> 5;
    CP_TILES(0, 0); CP_COMMIT();
    CP_TILES(1, 1); CP_COMMIT();
    int buf = 0, nxt = 2;
    for (int ch = 0; ch < nch; ch++) {
        if (ch + 1 < nch) { CP_WAIT(1); } else { CP_WAIT(0); }
        __syncthreads();
        if (ch + 2 < nch) {
            CP_TILES(ch + 2, nxt);
            CP_COMMIT();
        }
        COMPUTE(buf);
        buf = (buf + 1 == NSTAGE) ? 0 : buf + 1;
        nxt = (nxt + 1 == NSTAGE) ? 0 : nxt + 1;
    }

    // ---------------- epilogue ----------------
    const float NEG_INF = __int_as_float(0xff800000);
    const int gid = lane >> 2, q4 = lane & 3;
    const int vmode = qkv_mode && (n0 >= 512);

    if (!vmode) {
        float* C32b = C32 ? (C32 + bz * sC) : nullptr;
        __half* Chb = Ch ? (Ch + bz * sC) : nullptr;
        __half* Clb = Cl ? (Cl + bz * sC) : nullptr;
        const int* mk = maskp ? (maskp + bz * sMask) : nullptr;
#pragma unroll
        for (int mt = 0; mt < 4; mt++) {
#pragma unroll
            for (int nt = 0; nt < 4; nt++) {
                const int col = n0 + warp_n * 32 + nt * 8 + q4 * 2;
                float b0 = 0.f, b1 = 0.f;
                if (bias_n) { b0 = bias_n[col]; b1 = bias_n[col + 1]; }
#pragma unroll
                for (int h = 0; h < 2; h++) {
                    const int row = m0 + warp_m * 64 + mt * 16 + gid + h * 8;
                    float v0 = acc[mt][nt][h * 2 + 0] * alpha + b0;
                    float v1 = acc[mt][nt][h * 2 + 1] * alpha + b1;
                    if (mk) {
                        int2 mv = *reinterpret_cast<const int2*>(mk + (long long)row * 1024 + col);
                        if (mv.x != 0) v0 = NEG_INF;
                        if (mv.y != 0) v1 = NEG_INF;
                    }
                    if (C32b)
                        *reinterpret_cast<float2*>(C32b + (long long)row * ldc + col) =
                            make_float2(v0, v1);
                    if (Chb) {
                        __half2 hh, ll;
                        split2(v0, v1, hh, ll);
                        *reinterpret_cast<__half2*>(Chb + (long long)row * ldc + col) = hh;
                        *reinterpret_cast<__half2*>(Clb + (long long)row * ldc + col) = ll;
                    }
                }
            }
        }
    } else {
        // V part of QKV: stage transposed in SMEM, then coalesced 16B stores.
        __syncthreads();                       // mainloop SMEM reads complete
        __half* sh = reinterpret_cast<__half*>(smem);          // [128 d][136]
        __half* sl = sh + 128 * 136;
#pragma unroll
        for (int mt = 0; mt < 4; mt++) {
#pragma unroll
            for (int nt = 0; nt < 4; nt++) {
                const int cl0 = warp_n * 32 + nt * 8 + q4 * 2;  // local d
                const float b0 = bias_n[n0 + cl0];
                const float b1 = bias_n[n0 + cl0 + 1];
#pragma unroll
                for (int h = 0; h < 2; h++) {
                    const int rl = warp_m * 64 + mt * 16 + gid + h * 8;  // local t
                    float v0 = acc[mt][nt][h * 2 + 0] + b0;
                    float v1 = acc[mt][nt][h * 2 + 1] + b1;
                    __half h0 = __float2half_rn(v0), h1 = __float2half_rn(v1);
                    sh[cl0 * 136 + rl] = h0;
                    sh[(cl0 + 1) * 136 + rl] = h1;
                    sl[cl0 * 136 + rl] = __float2half_rn(v0 - __half2float(h0));
                    sl[(cl0 + 1) * 136 + rl] = __float2half_rn(v1 - __half2float(h1));
                }
            }
        }
        __syncthreads();
        __half* VThb = VTh + bz * (256ll * 1024);
        __half* VTlb = VTl + bz * (256ll * 1024);
#pragma unroll
        for (int i = tid; i < 128 * 16; i += 256) {
            const int d = i >> 4, seg = i & 15;
            uint4 uh = *reinterpret_cast<const uint4*>(&sh[d * 136 + seg * 8]);
            uint4 ul = *reinterpret_cast<const uint4*>(&sl[d * 136 + seg * 8]);
            const long long o = (long long)(n0 - 512 + d) * 1024 + m0 + seg * 8;
            *reinterpret_cast<uint4*>(&VThb[o]) = uh;
            *reinterpret_cast<uint4*>(&VTlb[o]) = ul;
        }
    }
}

// ---------------- transpose x: (bc, 256, 1024) -> (bc, 1024, 256) hi/lo halves ----
__global__ __launch_bounds__(256) void transpose_kernel(
    const float* __restrict__ x, __half* __restrict__ xh, __half* __restrict__ xl)
{
    __shared__ float tile[32][33];
    const int bz = blockIdx.z;
    const float* xs = x + (long long)bz * 256 * 1024;
    __half* xhd = xh + (long long)bz * 1024 * 256;
    __half* xld = xl + (long long)bz * 1024 * 256;
    const int t0 = blockIdx.x * 32, d0 = blockIdx.y * 32;
    const int tx = threadIdx.x, ty = threadIdx.y;
#pragma unroll
    for (int k = 0; k < 4; k++)
        tile[ty + k * 8][tx] = xs[(long long)(d0 + ty + k * 8) * 1024 + t0 + tx];
    __syncthreads();
#pragma unroll
    for (int k = 0; k < 4; k++) {
        float v = tile[tx][ty + k * 8];
        __half h = __float2half_rn(v);
        long long o = (long long)(t0 + ty + k * 8) * 256 + d0 + tx;
        xhd[o] = h;
        xld[o] = __float2half_rn(v - __half2float(h));
    }
}

// ---------------- weight fp32 -> hi/lo halves ----------------
__global__ void cvt_kernel(const float* __restrict__ w,
                           __half* __restrict__ h, __half* __restrict__ l, int n)
{
    int i = blockIdx.x * 256 + threadIdx.x;
    if (i < n) {
        float v = w[i];
        __half hh = __float2half_rn(v);
        h[i] = hh;
        l[i] = __float2half_rn(v - __half2float(hh));
    }
}

// ---------------- row softmax (fp32 in) -> P hi/lo halves ----------------
__global__ __launch_bounds__(256) void softmax_kernel(
    const float* __restrict__ S, __half* __restrict__ Ph, __half* __restrict__ Pl)
{
    const long long row = blockIdx.x;
    const float* p = S + row * 1024;
    const int tid = threadIdx.x;

    float4 v = reinterpret_cast<const float4*>(p)[tid];
    float m = fmaxf(fmaxf(v.x, v.y), fmaxf(v.z, v.w));
#pragma unroll
    for (int o = 16; o; o >>= 1) m = fmaxf(m, __shfl_xor_sync(0xffffffffu, m, o));

    __shared__ float red[8];
    if ((tid & 31) == 0) red[tid >> 5] = m;
    __syncthreads();
    float mm = red[0];
#pragma unroll
    for (int w = 1; w < 8; w++) mm = fmaxf(mm, red[w]);
    __syncthreads();

    float e0 = (v.x <= -1e30f) ? 0.f : __expf(v.x - mm);
    float e1 = (v.y <= -1e30f) ? 0.f : __expf(v.y - mm);
    float e2 = (v.z <= -1e30f) ? 0.f : __expf(v.z - mm);
    float e3 = (v.w <= -1e30f) ? 0.f : __expf(v.w - mm);

    float s = e0 + e1 + e2 + e3;
#pragma unroll
    for (int o = 16; o; o >>= 1) s += __shfl_xor_sync(0xffffffffu, s, o);
    if ((tid & 31) == 0) red[tid >> 5] = s;
    __syncthreads();
    float tot = red[0];
#pragma unroll
    for (int w = 1; w < 8; w++) tot += red[w];

    float inv = 1.0f / tot;
    float o0 = e0 * inv, o1 = e1 * inv, o2 = e2 * inv, o3 = e3 * inv;
    __half2 h01, l01, h23, l23;
    split2(o0, o1, h01, l01);
    split2(o2, o3, h23, l23);
    *reinterpret_cast<uint2*>(Ph + row * 1024 + tid * 4) =
        make_uint2(*reinterpret_cast<uint32_t*>(&h01), *reinterpret_cast<uint32_t*>(&h23));
    *reinterpret_cast<uint2*>(Pl + row * 1024 + tid * 4) =
        make_uint2(*reinterpret_cast<uint32_t*>(&l01), *reinterpret_cast<uint32_t*>(&l23));
}

extern "C" void kernel_launch(void* const* d_in, const int* in_sizes, int n_in,
                              void* d_out, int out_size)
{
    const float* x     = (const float*)d_in[0];   // (8,4,256,1024)
    const int*   mask  = (const int*)d_in[1];     // (8,4,1024,1024) bool -> int32
    const float* w_qkv = (const float*)d_in[2];   // (768,256)
    const float* b_qkv = (const float*)d_in[3];   // (768,)
    const float* w_out = (const float*)d_in[4];   // (256,256)
    const float* b_out = (const float*)d_in[5];   // (256,)
    float*       out   = (float*)d_out;           // (8,4,1024,256)

    __half *xth, *xtl, *qkh, *qkl, *vth, *vtl, *ph, *pl, *aoh, *aol, *wqh, *wql, *woh, *wol;
    float* scores;
    cudaGetSymbolAddress((void**)&xth, g_xt_h); cudaGetSymbolAddress((void**)&xtl, g_xt_l);
    cudaGetSymbolAddress((void**)&qkh, g_qk_h); cudaGetSymbolAddress((void**)&qkl, g_qk_l);
    cudaGetSymbolAddress((void**)&vth, g_vt_h); cudaGetSymbolAddress((void**)&vtl, g_vt_l);
    cudaGetSymbolAddress((void**)&ph,  g_p_h);  cudaGetSymbolAddress((void**)&pl,  g_p_l);
    cudaGetSymbolAddress((void**)&aoh, g_ao_h); cudaGetSymbolAddress((void**)&aol, g_ao_l);
    cudaGetSymbolAddress((void**)&wqh, g_wq_h); cudaGetSymbolAddress((void**)&wql, g_wq_l);
    cudaGetSymbolAddress((void**)&woh, g_wo_h); cudaGetSymbolAddress((void**)&wol, g_wo_l);
    cudaGetSymbolAddress((void**)&scores, g_scores);

    cudaFuncSetAttribute(hgemm, cudaFuncAttributeMaxDynamicSharedMemorySize, SMEM_BYTES);

    // 0) converters
    transpose_kernel<<<dim3(32, 8, 32), dim3(32, 8)>>>(x, xth, xtl);
    cvt_kernel<<<768, 256>>>(w_qkv, wqh, wql, 768 * 256);
    cvt_kernel<<<256, 256>>>(w_out, woh, wol, 256 * 256);

    // 1) QKV: Q,K -> qk halves; V -> vt halves (transposed)
    hgemm<<<dim3(6, 8, 32), 256, SMEM_BYTES>>>(
        xth, xtl, wqh, wql,
        nullptr, qkh, qkl, vth, vtl,
        256, 256, 256, 512,
        1024ll * 256, 0, 1024ll * 512,
        1.0f, b_qkv, nullptr, 0, 1);

    // 2) scores (fp32) = scale * Q @ K^T, mask -> -inf
    hgemm<<<dim3(8, 8, 32), 256, SMEM_BYTES>>>(
        qkh, qkl, qkh + 256, qkl + 256,
        scores, nullptr, nullptr, nullptr, nullptr,
        256, 512, 512, 1024,
        1024ll * 512, 1024ll * 512, 1024ll * 1024,
        0.0625f, nullptr, mask, 1024ll * 1024, 0);

    // 3) softmax -> P halves
    softmax_kernel<<<32 * 1024, 256>>>(scores, ph, pl);

    // 4) attnO halves = P @ V
    hgemm<<<dim3(2, 8, 32), 256, SMEM_BYTES>>>(
        ph, pl, vth, vtl,
        nullptr, aoh, aol, nullptr, nullptr,
        1024, 1024, 1024, 256,
        1024ll * 1024, 256ll * 1024, 1024ll * 256,
        1.0f, nullptr, nullptr, 0, 0);

    // 5) out (fp32) = attnO @ w_out^T + b_out
    hgemm<<<dim3(2, 8, 32), 256, SMEM_BYTES>>>(
        aoh, aol, woh, wol,
        out, nullptr, nullptr, nullptr, nullptr,
        256, 256, 256, 256,
        1024ll * 256, 0, 1024ll * 256,
        1.0f, b_out, nullptr, 0, 0);
}

// round 8
// speedup vs baseline: 1.2092x; 1.0016x over previous
#include <cuda_runtime.h>
#include <cuda_fp16.h>
#include <cstdint>

// ---------------- scratch: hi plane at [0], lo plane at [N] ----------------
#define XT_N (32ll * 1024 * 256)
#define QK_N (32ll * 1024 * 512)
#define VT_N (32ll * 256 * 1024)
#define P_N  (32ll * 1024 * 1024)
#define AO_N (32ll * 1024 * 256)
#define WQ_N (768ll * 256)
#define WO_N (256ll * 256)

__device__ __half g_xt[2 * XT_N];
__device__ __half g_qk[2 * QK_N];
__device__ __half g_vt[2 * VT_N];
__device__ __half g_p [2 * P_N];
__device__ __half g_ao[2 * AO_N];
__device__ __half g_wq[2 * WQ_N];
__device__ __half g_wo[2 * WO_N];
__device__ float  g_scores[32ll * 1024 * 1024];

__device__ __forceinline__ uint32_t smem_u32(const void* p) {
    uint32_t a;
    asm("{ .reg .u64 t; cvta.to.shared.u64 t, %1; cvt.u32.u64 %0, t; }" : "=r"(a) : "l"(p));
    return a;
}

#define CP_ASYNC16(dst, src) \
    asm volatile("cp.async.cg.shared.global [%0], [%1], 16;" :: "r"(dst), "l"(src))
#define CP_COMMIT() asm volatile("cp.async.commit_group;")
#define CP_WAIT(n)  asm volatile("cp.async.wait_group %0;" :: "n"(n))

#define LDSM4(r0, r1, r2, r3, addr)                                               \
    asm volatile("ldmatrix.sync.aligned.m8n8.x4.shared.b16 {%0,%1,%2,%3}, [%4];"  \
                 : "=r"(r0), "=r"(r1), "=r"(r2), "=r"(r3) : "r"(addr))

#define MMA16816(c, a, b0, b1)                                                    \
    asm volatile("mma.sync.aligned.m16n8k16.row.col.f32.f16.f16.f32 "             \
                 "{%0,%1,%2,%3},{%4,%5,%6,%7},{%8,%9},{%0,%1,%2,%3};"             \
                 : "+f"((c)[0]), "+f"((c)[1]), "+f"((c)[2]), "+f"((c)[3])         \
                 : "r"((a)[0]), "r"((a)[1]), "r"((a)[2]), "r"((a)[3]),            \
                   "r"(b0), "r"(b1))

// Compact tile: 128 rows x 32 halves = 64 B/row, XOR-swizzled 16B chunks.
#define TILE_B   8192
#define OFF_AH   0
#define OFF_AL   8192
#define OFF_BH   16384
#define OFF_BL   24576
#define BUF_B    32768
#define NSTAGE   3
#define SMEM_BYTES (NSTAGE * BUF_B)        // 98304 B

__device__ __forceinline__ uint32_t sws(int row, int khalf) {
    return (uint32_t)(row * 64 + ((((khalf >> 3) ^ (row >> 1)) & 3) << 4));
}

__device__ __forceinline__ void split2(float v0, float v1, __half2& h, __half2& l) {
    __half h0 = __float2half_rn(v0), h1 = __float2half_rn(v1);
    h = __halves2half2(h0, h1);
    l = __halves2half2(__float2half_rn(v0 - __half2float(h0)),
                       __float2half_rn(v1 - __half2float(h1)));
}

// C[128 x 128 tile] = A(m,k) . B(n,k)^T, fp32-equivalent via fp16 hi/lo 3-pass.
// All dims/strides compile-time. lo plane = hi pointer + LOFF.
template<int K, int LDA, int LDB, int LDC,
         long long SA, long long SB, long long SC,
         long long LOFFA, long long LOFFB,
         bool HAS_BIAS, bool HAS_MASK, bool OUT_F32, bool OUT_HALF, bool QKV>
__global__ __launch_bounds__(256, 2) void hgemm(
    const __half* __restrict__ Ah, const __half* __restrict__ Bh,
    float* __restrict__ C32, __half* __restrict__ Ch, __half* __restrict__ Cl,
    __half* __restrict__ VTh, __half* __restrict__ VTl,
    float alpha, const float* __restrict__ bias_n, const int* __restrict__ maskp)
{
    extern __shared__ char smem[];
    const uint32_t sbase = smem_u32(smem);
    const int tid = threadIdx.x;
    const int wid = tid >> 5, lane = tid & 31;
    const int bz = blockIdx.z;
    const int n0 = blockIdx.x * 128, m0 = blockIdx.y * 128;
    const int warp_m = wid & 1, warp_n = wid >> 1;   // 2 x 4 warp grid

    const __half* Ahb = Ah + bz * SA + (long long)m0 * LDA;
    const __half* Bhb = Bh + bz * SB + (long long)n0 * LDB;

    float acc[4][4][4];
#pragma unroll
    for (int mt = 0; mt < 4; mt++)
#pragma unroll
        for (int nt = 0; nt < 4; nt++)
#pragma unroll
            for (int r = 0; r < 4; r++) acc[mt][nt][r] = 0.f;

    auto CP_TILES = [&](int ch, int buf) {
        const int k0 = ch << 5;
        const uint32_t sb = sbase + buf * BUF_B;
#pragma unroll
        for (int i = 0; i < 2; i++) {
            const int c = tid + i * 256;            // 0..511
            const int row = c >> 2, part = c & 3;
            const uint32_t doff = sws(row, part << 3);
            const __half* ga = Ahb + (long long)row * LDA + k0 + part * 8;
            const __half* gb = Bhb + (long long)row * LDB + k0 + part * 8;
            CP_ASYNC16(sb + OFF_AH + doff, ga);
            CP_ASYNC16(sb + OFF_AL + doff, ga + LOFFA);
            CP_ASYNC16(sb + OFF_BH + doff, gb);
            CP_ASYNC16(sb + OFF_BL + doff, gb + LOFFB);
        }
    };

    // lane-derived ldmatrix row/col bases
    const int a_row = warp_m * 64 + (lane & 7) + ((lane >> 3) & 1) * 8;
    const int a_kq  = (lane >> 4) * 8;
    const int b_row = warp_n * 32 + (lane >> 4) * 8 + (lane & 7);
    const int b_kq  = ((lane >> 3) & 1) * 8;

    auto COMPUTE = [&](int buf) {
        const uint32_t o = sbase + buf * BUF_B;
#pragma unroll
        for (int s = 0; s < 2; s++) {
            uint32_t bh[8], bl[8];
#pragma unroll
            for (int p = 0; p < 2; p++) {
                const int row = b_row + p * 16;
                const uint32_t boff = sws(row, s * 16 + b_kq);
                LDSM4(bh[p * 4 + 0], bh[p * 4 + 1], bh[p * 4 + 2], bh[p * 4 + 3], o + OFF_BH + boff);
                LDSM4(bl[p * 4 + 0], bl[p * 4 + 1], bl[p * 4 + 2], bl[p * 4 + 3], o + OFF_BL + boff);
            }
#pragma unroll
            for (int mt = 0; mt < 4; mt++) {
                uint32_t ah[4], al[4];
                const int row = a_row + mt * 16;
                const uint32_t aoff = sws(row, s * 16 + a_kq);
                LDSM4(ah[0], ah[1], ah[2], ah[3], o + OFF_AH + aoff);
                LDSM4(al[0], al[1], al[2], al[3], o + OFF_AL + aoff);
#pragma unroll
                for (int nt = 0; nt < 4; nt++) {
                    const int i0 = (nt >> 1) * 4 + (nt & 1) * 2;
                    MMA16816(acc[mt][nt], ah, bh[i0], bh[i0 + 1]);
                    MMA16816(acc[mt][nt], ah, bl[i0], bl[i0 + 1]);
                    MMA16816(acc[mt][nt], al, bh[i0], bh[i0 + 1]);
                }
            }
        }
    };

    // 3-stage pipeline, one barrier per chunk; static trip count.
    constexpr int nch = K >> 5;
    CP_TILES(0, 0); CP_COMMIT();
    CP_TILES(1, 1); CP_COMMIT();
    int buf = 0, nxt = 2;
#pragma unroll 2
    for (int ch = 0; ch < nch; ch++) {
        if (ch + 1 < nch) { CP_WAIT(1); } else { CP_WAIT(0); }
        __syncthreads();
        if (ch + 2 < nch) {
            CP_TILES(ch + 2, nxt);
            CP_COMMIT();
        }
        COMPUTE(buf);
        buf = (buf + 1 == NSTAGE) ? 0 : buf + 1;
        nxt = (nxt + 1 == NSTAGE) ? 0 : nxt + 1;
    }

    // ---------------- epilogue ----------------
    const float NEG_INF = __int_as_float(0xff800000);
    const int gid = lane >> 2, q4 = lane & 3;
    const bool vmode = QKV && (n0 >= 512);

    if (!vmode) {
        float* C32b = OUT_F32 ? (C32 + bz * SC) : nullptr;
        __half* Chb = OUT_HALF ? (Ch + bz * SC) : nullptr;
        __half* Clb = OUT_HALF ? (Cl + bz * SC) : nullptr;
        const int* mk = HAS_MASK ? (maskp + bz * SC) : nullptr;
#pragma unroll
        for (int mt = 0; mt < 4; mt++) {
#pragma unroll
            for (int nt = 0; nt < 4; nt++) {
                const int col = n0 + warp_n * 32 + nt * 8 + q4 * 2;
                float b0 = 0.f, b1 = 0.f;
                if (HAS_BIAS) { b0 = bias_n[col]; b1 = bias_n[col + 1]; }
#pragma unroll
                for (int h = 0; h < 2; h++) {
                    const int row = m0 + warp_m * 64 + mt * 16 + gid + h * 8;
                    float v0 = acc[mt][nt][h * 2 + 0] * alpha + b0;
                    float v1 = acc[mt][nt][h * 2 + 1] * alpha + b1;
                    if (HAS_MASK) {
                        int2 mv = *reinterpret_cast<const int2*>(mk + (long long)row * 1024 + col);
                        if (mv.x != 0) v0 = NEG_INF;
                        if (mv.y != 0) v1 = NEG_INF;
                    }
                    if (OUT_F32)
                        *reinterpret_cast<float2*>(C32b + (long long)row * LDC + col) =
                            make_float2(v0, v1);
                    if (OUT_HALF) {
                        __half2 hh, ll;
                        split2(v0, v1, hh, ll);
                        *reinterpret_cast<__half2*>(Chb + (long long)row * LDC + col) = hh;
                        *reinterpret_cast<__half2*>(Clb + (long long)row * LDC + col) = ll;
                    }
                }
            }
        }
    } else {
        // V part of QKV: stage transposed in SMEM, then coalesced 16B stores.
        __syncthreads();
        __half* sh = reinterpret_cast<__half*>(smem);          // [128 d][136]
        __half* sl = sh + 128 * 136;
#pragma unroll
        for (int mt = 0; mt < 4; mt++) {
#pragma unroll
            for (int nt = 0; nt < 4; nt++) {
                const int cl0 = warp_n * 32 + nt * 8 + q4 * 2;  // local d
                const float b0 = bias_n[n0 + cl0];
                const float b1 = bias_n[n0 + cl0 + 1];
#pragma unroll
                for (int h = 0; h < 2; h++) {
                    const int rl = warp_m * 64 + mt * 16 + gid + h * 8;  // local t
                    float v0 = acc[mt][nt][h * 2 + 0] + b0;
                    float v1 = acc[mt][nt][h * 2 + 1] + b1;
                    __half h0 = __float2half_rn(v0), h1 = __float2half_rn(v1);
                    sh[cl0 * 136 + rl] = h0;
                    sh[(cl0 + 1) * 136 + rl] = h1;
                    sl[cl0 * 136 + rl] = __float2half_rn(v0 - __half2float(h0));
                    sl[(cl0 + 1) * 136 + rl] = __float2half_rn(v1 - __half2float(h1));
                }
            }
        }
        __syncthreads();
        __half* VThb = VTh + bz * (256ll * 1024);
        __half* VTlb = VTl + bz * (256ll * 1024);
#pragma unroll
        for (int i = tid; i < 128 * 16; i += 256) {
            const int d = i >> 4, seg = i & 15;
            uint4 uh = *reinterpret_cast<const uint4*>(&sh[d * 136 + seg * 8]);
            uint4 ul = *reinterpret_cast<const uint4*>(&sl[d * 136 + seg * 8]);
            const long long o2 = (long long)(n0 - 512 + d) * 1024 + m0 + seg * 8;
            *reinterpret_cast<uint4*>(&VThb[o2]) = uh;
            *reinterpret_cast<uint4*>(&VTlb[o2]) = ul;
        }
    }
}

// ---------------- transpose x: (bc, 256, 1024) -> (bc, 1024, 256) hi/lo ----------
__global__ __launch_bounds__(256) void transpose_kernel(
    const float* __restrict__ x, __half* __restrict__ xh, __half* __restrict__ xl)
{
    __shared__ float tile[32][33];
    const int bz = blockIdx.z;
    const float* xs = x + (long long)bz * 256 * 1024;
    __half* xhd = xh + (long long)bz * 1024 * 256;
    __half* xld = xl + (long long)bz * 1024 * 256;
    const int t0 = blockIdx.x * 32, d0 = blockIdx.y * 32;
    const int tx = threadIdx.x, ty = threadIdx.y;
#pragma unroll
    for (int k = 0; k < 4; k++)
        tile[ty + k * 8][tx] = xs[(long long)(d0 + ty + k * 8) * 1024 + t0 + tx];
    __syncthreads();
#pragma unroll
    for (int k = 0; k < 4; k++) {
        float v = tile[tx][ty + k * 8];
        __half h = __float2half_rn(v);
        long long o = (long long)(t0 + ty + k * 8) * 256 + d0 + tx;
        xhd[o] = h;
        xld[o] = __float2half_rn(v - __half2float(h));
    }
}

// ---------------- weight fp32 -> hi/lo halves ----------------
__global__ void cvt_kernel(const float* __restrict__ w,
                           __half* __restrict__ h, __half* __restrict__ l, int n)
{
    int i = blockIdx.x * 256 + threadIdx.x;
    if (i < n) {
        float v = w[i];
        __half hh = __float2half_rn(v);
        h[i] = hh;
        l[i] = __float2half_rn(v - __half2float(hh));
    }
}

// ---------------- row softmax (fp32 in) -> P hi/lo halves ----------------
__global__ __launch_bounds__(256) void softmax_kernel(
    const float* __restrict__ S, __half* __restrict__ Ph, __half* __restrict__ Pl)
{
    const long long row = blockIdx.x;
    const float* p = S + row * 1024;
    const int tid = threadIdx.x;

    float4 v = reinterpret_cast<const float4*>(p)[tid];
    float m = fmaxf(fmaxf(v.x, v.y), fmaxf(v.z, v.w));
#pragma unroll
    for (int o = 16; o; o >>= 1) m = fmaxf(m, __shfl_xor_sync(0xffffffffu, m, o));

    __shared__ float red[8];
    if ((tid & 31) == 0) red[tid >> 5] = m;
    __syncthreads();
    float mm = red[0];
#pragma unroll
    for (int w = 1; w < 8; w++) mm = fmaxf(mm, red[w]);
    __syncthreads();

    float e0 = (v.x <= -1e30f) ? 0.f : __expf(v.x - mm);
    float e1 = (v.y <= -1e30f) ? 0.f : __expf(v.y - mm);
    float e2 = (v.z <= -1e30f) ? 0.f : __expf(v.z - mm);
    float e3 = (v.w <= -1e30f) ? 0.f : __expf(v.w - mm);

    float s = e0 + e1 + e2 + e3;
#pragma unroll
    for (int o = 16; o; o >>= 1) s += __shfl_xor_sync(0xffffffffu, s, o);
    if ((tid & 31) == 0) red[tid >> 5] = s;
    __syncthreads();
    float tot = red[0];
#pragma unroll
    for (int w = 1; w < 8; w++) tot += red[w];

    float inv = 1.0f / tot;
    float o0 = e0 * inv, o1 = e1 * inv, o2 = e2 * inv, o3 = e3 * inv;
    __half2 h01, l01, h23, l23;
    split2(o0, o1, h01, l01);
    split2(o2, o3, h23, l23);
    *reinterpret_cast<uint2*>(Ph + row * 1024 + tid * 4) =
        make_uint2(*reinterpret_cast<uint32_t*>(&h01), *reinterpret_cast<uint32_t*>(&h23));
    *reinterpret_cast<uint2*>(Pl + row * 1024 + tid * 4) =
        make_uint2(*reinterpret_cast<uint32_t*>(&l01), *reinterpret_cast<uint32_t*>(&l23));
}

extern "C" void kernel_launch(void* const* d_in, const int* in_sizes, int n_in,
                              void* d_out, int out_size)
{
    const float* x     = (const float*)d_in[0];   // (8,4,256,1024)
    const int*   mask  = (const int*)d_in[1];     // (8,4,1024,1024) bool -> int32
    const float* w_qkv = (const float*)d_in[2];   // (768,256)
    const float* b_qkv = (const float*)d_in[3];   // (768,)
    const float* w_out = (const float*)d_in[4];   // (256,256)
    const float* b_out = (const float*)d_in[5];   // (256,)
    float*       out   = (float*)d_out;           // (8,4,1024,256)

    __half *xt, *qk, *vt, *pp, *ao, *wq, *wo;
    float* scores;
    cudaGetSymbolAddress((void**)&xt, g_xt);
    cudaGetSymbolAddress((void**)&qk, g_qk);
    cudaGetSymbolAddress((void**)&vt, g_vt);
    cudaGetSymbolAddress((void**)&pp, g_p);
    cudaGetSymbolAddress((void**)&ao, g_ao);
    cudaGetSymbolAddress((void**)&wq, g_wq);
    cudaGetSymbolAddress((void**)&wo, g_wo);
    cudaGetSymbolAddress((void**)&scores, g_scores);

    // 0) converters
    transpose_kernel<<<dim3(32, 8, 32), dim3(32, 8)>>>(x, xt, xt + XT_N);
    cvt_kernel<<<768, 256>>>(w_qkv, wq, wq + WQ_N, 768 * 256);
    cvt_kernel<<<256, 256>>>(w_out, wo, wo + WO_N, 256 * 256);

    // 1) QKV: Q,K -> qk halves; V -> vt halves (transposed)
    {
        auto kfn = hgemm<256, 256, 256, 512, 1024ll * 256, 0ll, 1024ll * 512,
                         XT_N, WQ_N, true, false, false, true, true>;
        cudaFuncSetAttribute(kfn, cudaFuncAttributeMaxDynamicSharedMemorySize, SMEM_BYTES);
        kfn<<<dim3(6, 8, 32), 256, SMEM_BYTES>>>(
            xt, wq, nullptr, qk, qk + QK_N, vt, vt + VT_N, 1.0f, b_qkv, nullptr);
    }

    // 2) scores (fp32) = scale * Q @ K^T, mask -> -inf
    {
        auto kfn = hgemm<256, 512, 512, 1024, 1024ll * 512, 1024ll * 512, 1024ll * 1024,
                         QK_N, QK_N, false, true, true, false, false>;
        cudaFuncSetAttribute(kfn, cudaFuncAttributeMaxDynamicSharedMemorySize, SMEM_BYTES);
        kfn<<<dim3(8, 8, 32), 256, SMEM_BYTES>>>(
            qk, qk + 256, scores, nullptr, nullptr, nullptr, nullptr,
            0.0625f, nullptr, mask);
    }

    // 3) softmax -> P halves
    softmax_kernel<<<32 * 1024, 256>>>(scores, pp, pp + P_N);

    // 4) attnO halves = P @ V
    {
        auto kfn = hgemm<1024, 1024, 1024, 256, 1024ll * 1024, 256ll * 1024, 1024ll * 256,
                         P_N, VT_N, false, false, false, true, false>;
        cudaFuncSetAttribute(kfn, cudaFuncAttributeMaxDynamicSharedMemorySize, SMEM_BYTES);
        kfn<<<dim3(2, 8, 32), 256, SMEM_BYTES>>>(
            pp, vt, nullptr, ao, ao + AO_N, nullptr, nullptr, 1.0f, nullptr, nullptr);
    }

    // 5) out (fp32) = attnO @ w_out^T + b_out
    {
        auto kfn = hgemm<256, 256, 256, 256, 1024ll * 256, 0ll, 1024ll * 256,
                         AO_N, WO_N, true, false, true, false, false>;
        cudaFuncSetAttribute(kfn, cudaFuncAttributeMaxDynamicSharedMemorySize, SMEM_BYTES);
        kfn<<<dim3(2, 8, 32), 256, SMEM_BYTES>>>(
            ao, wo, out, nullptr, nullptr, nullptr, nullptr, 1.0f, b_out, nullptr);
    }
}